// round 14
// baseline (speedup 1.0000x reference)
#include <cuda_runtime.h>
#include <cuda_fp16.h>
#include <cstdint>

#define NR 65536
#define CIN 256
#define COUT 128
#define KOFF 8
#define CNTF 524288.0f

#define BM 128
#define BNC 256                    // CTA N tile (2 k-offsets)
#define OFFB 10240                 // A bytes per stage (128*80)
#define STAGEB 30720               // A 10240 + B 20480
#define NSTAGE 4
#define OFF_STATS (NSTAGE * STAGEB)
#define SMEM_BYTES (OFF_STATS + 1024)

__device__ __align__(16) __half g_Xh[NR * CIN];           // fp16 X
__device__ __align__(16) __half g_Wh[KOFF * COUT * CIN];  // [n=k*128+d][c] fp16
__device__ __align__(16) float g_sum[COUT];
__device__ __align__(16) float g_sumsq[COUT];
__device__ __align__(16) float g_sa[COUT];
__device__ __align__(16) float g_sb[COUT];

__device__ __forceinline__ uint32_t smem_u32(const void* p) {
    uint32_t a;
    asm("{ .reg .u64 t; cvta.to.shared.u64 t, %1; cvt.u32.u64 %0, t; }" : "=r"(a) : "l"(p));
    return a;
}
__device__ __forceinline__ void cpa16(uint32_t s, const void* g) {
    asm volatile("cp.async.cg.shared.global [%0], [%1], 16;" :: "r"(s), "l"(g));
}
#define CP_COMMIT() asm volatile("cp.async.commit_group;" ::: "memory")
#define CP_WAIT2()  asm volatile("cp.async.wait_group 2;" ::: "memory")
#define CP_WAIT1()  asm volatile("cp.async.wait_group 1;" ::: "memory")
#define CP_WAIT0()  asm volatile("cp.async.wait_group 0;" ::: "memory")

__device__ __forceinline__ void ldsm4(uint32_t* r, uint32_t a) {
    asm volatile("ldmatrix.sync.aligned.m8n8.x4.shared.b16 {%0,%1,%2,%3}, [%4];"
        : "=r"(r[0]), "=r"(r[1]), "=r"(r[2]), "=r"(r[3]) : "r"(a));
}
__device__ __forceinline__ void mma16(float* c, const uint32_t* a, uint32_t b0, uint32_t b1) {
    asm volatile(
        "mma.sync.aligned.m16n8k16.row.col.f32.f16.f16.f32 "
        "{%0,%1,%2,%3}, {%4,%5,%6,%7}, {%8,%9}, {%0,%1,%2,%3};"
        : "+f"(c[0]), "+f"(c[1]), "+f"(c[2]), "+f"(c[3])
        : "r"(a[0]), "r"(a[1]), "r"(a[2]), "r"(a[3]), "r"(b0), "r"(b1));
}

__global__ void k_zero() {
    int t = threadIdx.x;
    if (t < COUT) { g_sum[t] = 0.f; g_sumsq[t] = 0.f; }
}

__global__ __launch_bounds__(256) void k_xh(const float* __restrict__ X) {
    int i = (blockIdx.x * 256 + threadIdx.x) * 8;
    float4 v0 = *(const float4*)&X[i];
    float4 v1 = *(const float4*)&X[i + 4];
    __half2 h[4];
    h[0] = __floats2half2_rn(v0.x, v0.y); h[1] = __floats2half2_rn(v0.z, v0.w);
    h[2] = __floats2half2_rn(v1.x, v1.y); h[3] = __floats2half2_rn(v1.z, v1.w);
    *(uint4*)&g_Xh[i] = *(uint4*)h;
}

__global__ __launch_bounds__(256) void k_wt(const float* __restrict__ W) {
    int idx = blockIdx.x * 256 + threadIdx.x;   // 262144
    int n = idx >> 8, c = idx & 255;
    int k = n >> 7, d = n & 127;
    g_Wh[idx] = __float2half(W[(k << 15) + (c << 7) + d]);
}

__global__ __launch_bounds__(256, 1)
void k_gemm(float* __restrict__ out) {
    extern __shared__ char smem[];
    float* ssum = (float*)(smem + OFF_STATS);
    float* ssq  = ssum + COUT;

    const int tid = threadIdx.x, lane = tid & 31, wid = tid >> 5;
    const int wm = wid >> 2, wn = wid & 3;       // 2x4 warps, 64x64 tiles
    const int bx = blockIdx.x;                   // k-offset pair 0..3
    const int m0 = blockIdx.y * BM;

    if (tid < COUT) { ssum[tid] = 0.f; ssq[tid] = 0.f; }

    const __half* Ag = g_Xh + (size_t)m0 * CIN;
    const __half* Bg = g_Wh + (size_t)(bx * BNC) * CIN;
    const uint32_t smb = smem_u32(smem);

    // cp.async coords: A 512 granules (2/thr), B 1024 granules (4/thr)
    int rA[2], gA[2], rB[4], gB[4];
#pragma unroll
    for (int i = 0; i < 2; i++) {
        int f = tid + 256 * i;
        rA[i] = f >> 2; gA[i] = f & 3;
    }
#pragma unroll
    for (int i = 0; i < 4; i++) {
        int f = tid + 256 * i;
        rB[i] = f >> 2; gB[i] = f & 3;
    }

#define ISSUE(t, b) do {                                                          \
        uint32_t base = smb + (uint32_t)(b) * STAGEB;                             \
        _Pragma("unroll")                                                         \
        for (int i = 0; i < 2; i++)                                               \
            cpa16(base + (uint32_t)(rA[i] * 80 + gA[i] * 16),                     \
                  Ag + rA[i] * CIN + 32 * (t) + gA[i] * 8);                       \
        _Pragma("unroll")                                                         \
        for (int i = 0; i < 4; i++)                                               \
            cpa16(base + OFFB + (uint32_t)(rB[i] * 80 + gB[i] * 16),              \
                  Bg + rB[i] * CIN + 32 * (t) + gB[i] * 8);                       \
        CP_COMMIT();                                                              \
    } while (0)

    float c[4][8][4];
#pragma unroll
    for (int mt = 0; mt < 4; mt++)
#pragma unroll
        for (int nt = 0; nt < 8; nt++)
#pragma unroll
            for (int l = 0; l < 4; l++) c[mt][nt][l] = 0.f;

    const int grp = lane >> 3, lr = lane & 7;
    const uint32_t aoff = (uint32_t)((wm * 64 + (grp & 1) * 8 + lr) * 80 + (grp >> 1) * 16);
    const uint32_t boff = (uint32_t)(OFFB + (wn * 64 + (grp >> 1) * 8 + lr) * 80 + (grp & 1) * 16);

    ISSUE(0, 0);
    ISSUE(1, 1);
    ISSUE(2, 2);

#pragma unroll
    for (int t = 0; t < 8; t++) {
        if (t <= 5) CP_WAIT2(); else if (t == 6) CP_WAIT1(); else CP_WAIT0();
        __syncthreads();
        if (t < 5) ISSUE(t + 3, (t + 3) & 3);

        const uint32_t stg = smb + (uint32_t)(t & 3) * STAGEB;
#pragma unroll
        for (int ks = 0; ks < 2; ks++) {
            uint32_t a[4][4], b[4][4];
#pragma unroll
            for (int mt = 0; mt < 4; mt++)
                ldsm4(a[mt], stg + aoff + mt * (16 * 80) + ks * 32);
#pragma unroll
            for (int p = 0; p < 4; p++)
                ldsm4(b[p], stg + boff + p * (16 * 80) + ks * 32);
#pragma unroll
            for (int p = 0; p < 4; p++) {
#pragma unroll
                for (int mt = 0; mt < 4; mt++) {
                    mma16(c[mt][2 * p],     a[mt], b[p][0], b[p][1]);
                    mma16(c[mt][2 * p + 1], a[mt], b[p][2], b[p][3]);
                }
            }
        }
        __syncthreads();
    }

    // ---- epilogue: raw write + per-channel stats ----
    const int kof = 2 * bx + (wn >> 1);
    float* ow = out + ((size_t)kof * NR + m0) * COUT + (wn & 1) * 64;
#pragma unroll
    for (int mt = 0; mt < 4; mt++) {
        int r = wm * 64 + mt * 16 + (lane >> 2);
#pragma unroll
        for (int nt = 0; nt < 8; nt++) {
            int dc = nt * 8 + 2 * (lane & 3);
            *(float2*)&ow[(size_t)r * COUT + dc] =
                make_float2(c[mt][nt][0], c[mt][nt][1]);
            *(float2*)&ow[(size_t)(r + 8) * COUT + dc] =
                make_float2(c[mt][nt][2], c[mt][nt][3]);
        }
    }

#pragma unroll
    for (int nt = 0; nt < 8; nt++) {
        float s0 = 0.f, s1 = 0.f, q0 = 0.f, q1 = 0.f;
#pragma unroll
        for (int mt = 0; mt < 4; mt++) {
            float v0 = c[mt][nt][0], v1 = c[mt][nt][1];
            float v2 = c[mt][nt][2], v3 = c[mt][nt][3];
            s0 += v0 + v2;           s1 += v1 + v3;
            q0 += v0 * v0 + v2 * v2; q1 += v1 * v1 + v3 * v3;
        }
#pragma unroll
        for (int off = 4; off < 32; off <<= 1) {
            s0 += __shfl_xor_sync(0xffffffffu, s0, off);
            s1 += __shfl_xor_sync(0xffffffffu, s1, off);
            q0 += __shfl_xor_sync(0xffffffffu, q0, off);
            q1 += __shfl_xor_sync(0xffffffffu, q1, off);
        }
        if (lane < 4) {
            int col = (wn & 1) * 64 + nt * 8 + 2 * lane;
            atomicAdd(&ssum[col],     s0); atomicAdd(&ssum[col + 1], s1);
            atomicAdd(&ssq[col],      q0); atomicAdd(&ssq[col + 1],  q1);
        }
    }
    __syncthreads();
    if (tid < COUT) {
        atomicAdd(&g_sum[tid],   ssum[tid]);
        atomicAdd(&g_sumsq[tid], ssq[tid]);
    }
}

__global__ void k_stats(const float* __restrict__ gamma, const float* __restrict__ beta) {
    int t = threadIdx.x;
    if (t < COUT) {
        float mean = g_sum[t] / CNTF;
        float var  = g_sumsq[t] / CNTF - mean * mean;
        float A = gamma[t] * rsqrtf(var + 1e-5f);
        g_sa[t] = A;
        g_sb[t] = beta[t] - mean * A;
    }
}

__global__ __launch_bounds__(256) void k_bnrelu(float* __restrict__ o) {
    int i = blockIdx.x * 256 + threadIdx.x;
    float4* o4 = (float4*)o;
    const float4* a4 = (const float4*)g_sa;
    const float4* b4 = (const float4*)g_sb;
    float4 v = o4[i];
    float4 a = a4[i & 31], b = b4[i & 31];
    v.x = fmaxf(fmaf(v.x, a.x, b.x), 0.f);
    v.y = fmaxf(fmaf(v.y, a.y, b.y), 0.f);
    v.z = fmaxf(fmaf(v.z, a.z, b.z), 0.f);
    v.w = fmaxf(fmaf(v.w, a.w, b.w), 0.f);
    o4[i] = v;
}

extern "C" void kernel_launch(void* const* d_in, const int* in_sizes, int n_in,
                              void* d_out, int out_size) {
    const float* X     = (const float*)d_in[0];   // [65536, 256]
    const float* W     = (const float*)d_in[1];   // [8, 256, 128]
    const float* gamma = (const float*)d_in[2];   // [128]
    const float* beta  = (const float*)d_in[3];   // [128]
    float* out = (float*)d_out;                   // [8*65536, 128]

    cudaFuncSetAttribute(k_gemm, cudaFuncAttributeMaxDynamicSharedMemorySize, SMEM_BYTES);
    k_zero<<<1, 128>>>();                                     // launch 1
    k_xh<<<NR * CIN / (256 * 8), 256>>>(X);                   // launch 2
    k_wt<<<1024, 256>>>(W);                                   // launch 3
    k_gemm<<<dim3(4, NR / BM), 256, SMEM_BYTES>>>(out);       // launch 4 -> profiled
    k_stats<<<1, 128>>>(gamma, beta);
    k_bnrelu<<<(KOFF * NR * COUT) / 4 / 256, 256>>>(out);
}

// round 15
// speedup vs baseline: 1.2036x; 1.2036x over previous
#include <cuda_runtime.h>
#include <cuda_fp16.h>
#include <cstdint>

#define NR 65536
#define CIN 256
#define COUT 128
#define KOFF 8
#define CNTF 524288.0f

// ---- main GEMM (R13 config) ----
#define BM 128
#define OFFB 10240
#define STAGEB 20480
#define NSTAGE 3
#define OFF_STATS (NSTAGE * STAGEB)
#define SMEM_BYTES (OFF_STATS + 1024)

// ---- gram kernel ----
#define GPAD 272                   // bytes per smem row (136 halves)
#define GTILE (128 * GPAD)         // 34816 B per tile
#define GSTAGE (2 * GTILE)         // 69632 B (TA + TB)
#define GSMEM (2 * GSTAGE)         // 139264 B

__device__ __align__(16) __half g_Xh[NR * CIN];
__device__ __align__(16) __half g_Wh[KOFF * COUT * CIN];  // [n=k*128+d][c]
__device__ __align__(16) float g_G[CIN * CIN];            // Gram
__device__ __align__(16) float g_colsum[CIN];
__device__ __align__(16) float g_sa[COUT];
__device__ __align__(16) float g_sb[COUT];

__device__ __forceinline__ uint32_t smem_u32(const void* p) {
    uint32_t a;
    asm("{ .reg .u64 t; cvta.to.shared.u64 t, %1; cvt.u32.u64 %0, t; }" : "=r"(a) : "l"(p));
    return a;
}
__device__ __forceinline__ void cpa16(uint32_t s, const void* g) {
    asm volatile("cp.async.cg.shared.global [%0], [%1], 16;" :: "r"(s), "l"(g));
}
#define CP_COMMIT() asm volatile("cp.async.commit_group;" ::: "memory")
#define CP_WAIT1()  asm volatile("cp.async.wait_group 1;" ::: "memory")
#define CP_WAIT0()  asm volatile("cp.async.wait_group 0;" ::: "memory")

__device__ __forceinline__ void ldsm4(uint32_t* r, uint32_t a) {
    asm volatile("ldmatrix.sync.aligned.m8n8.x4.shared.b16 {%0,%1,%2,%3}, [%4];"
        : "=r"(r[0]), "=r"(r[1]), "=r"(r[2]), "=r"(r[3]) : "r"(a));
}
__device__ __forceinline__ void ldsm4t(uint32_t* r, uint32_t a) {
    asm volatile("ldmatrix.sync.aligned.m8n8.x4.trans.shared.b16 {%0,%1,%2,%3}, [%4];"
        : "=r"(r[0]), "=r"(r[1]), "=r"(r[2]), "=r"(r[3]) : "r"(a));
}
__device__ __forceinline__ void mma16(float* c, const uint32_t* a, uint32_t b0, uint32_t b1) {
    asm volatile(
        "mma.sync.aligned.m16n8k16.row.col.f32.f16.f16.f32 "
        "{%0,%1,%2,%3}, {%4,%5,%6,%7}, {%8,%9}, {%0,%1,%2,%3};"
        : "+f"(c[0]), "+f"(c[1]), "+f"(c[2]), "+f"(c[3])
        : "r"(a[0]), "r"(a[1]), "r"(a[2]), "r"(a[3]), "r"(b0), "r"(b1));
}

// X fp32 -> fp16 (+ zero G / colsum in low blocks)
__global__ __launch_bounds__(256) void k_xh(const float* __restrict__ X) {
    int idx = blockIdx.x * 256 + threadIdx.x;
    int i = idx * 8;
    float4 v0 = *(const float4*)&X[i];
    float4 v1 = *(const float4*)&X[i + 4];
    __half2 h[4];
    h[0] = __floats2half2_rn(v0.x, v0.y); h[1] = __floats2half2_rn(v0.z, v0.w);
    h[2] = __floats2half2_rn(v1.x, v1.y); h[3] = __floats2half2_rn(v1.z, v1.w);
    *(uint4*)&g_Xh[i] = *(uint4*)h;
    if (idx < CIN * CIN) g_G[idx] = 0.f;
    if (idx < CIN) g_colsum[idx] = 0.f;
}

__global__ __launch_bounds__(256) void k_wt(const float* __restrict__ W) {
    int idx = blockIdx.x * 256 + threadIdx.x;
    int n = idx >> 8, c = idx & 255;
    int k = n >> 7, d = n & 127;
    g_Wh[idx] = __float2half(W[(k << 15) + (c << 7) + d]);
}

// colsum of Xh (fp32)
__global__ __launch_bounds__(256) void k_colsum() {
    int c = threadIdx.x;
    int r0 = blockIdx.x * 256;
    float s = 0.f;
#pragma unroll 8
    for (int r = 0; r < 256; r++)
        s += __half2float(g_Xh[(size_t)(r0 + r) * CIN + c]);
    atomicAdd(&g_colsum[c], s);
}

// G += Xslice^T Xslice. grid (4, 64): bx -> (c1blk, c2blk), by -> 1024-row slice
__global__ __launch_bounds__(256, 1) void k_gram() {
    extern __shared__ char smem[];
    const uint32_t smb = smem_u32(smem);
    const int tid = threadIdx.x, lane = tid & 31, wid = tid >> 5;
    const int wm = wid >> 1, wn = wid & 1;        // 4x2 warps, 32x64
    const int c1blk = blockIdx.x & 1, c2blk = blockIdx.x >> 1;
    const int slice = blockIdx.y * 1024;

    const __half* XA = g_Xh + c1blk * 128;
    const __half* XB = g_Xh + c2blk * 128;

    int rT[8], gT[8];
#pragma unroll
    for (int i = 0; i < 8; i++) {
        int f = tid + i * 256;
        rT[i] = f >> 4; gT[i] = f & 15;
    }

#define GISSUE(ch, b) do {                                                        \
        uint32_t base = smb + (uint32_t)(b) * GSTAGE;                             \
        int r0 = slice + (ch) * 128;                                              \
        _Pragma("unroll")                                                         \
        for (int i = 0; i < 8; i++) {                                             \
            uint32_t so = (uint32_t)(rT[i] * GPAD + gT[i] * 16);                  \
            size_t go = (size_t)(r0 + rT[i]) * CIN + gT[i] * 8;                   \
            cpa16(base + so,         XA + go);                                    \
            cpa16(base + GTILE + so, XB + go);                                    \
        }                                                                         \
        CP_COMMIT();                                                              \
    } while (0)

    float c[2][8][4];
#pragma unroll
    for (int mt = 0; mt < 2; mt++)
#pragma unroll
        for (int nt = 0; nt < 8; nt++)
#pragma unroll
            for (int l = 0; l < 4; l++) c[mt][nt][l] = 0.f;

    const int grp = lane >> 3, lr = lane & 7;

    GISSUE(0, 0);
#pragma unroll
    for (int ch = 0; ch < 8; ch++) {
        CP_WAIT0();
        __syncthreads();
        if (ch < 7) GISSUE(ch + 1, (ch + 1) & 1);

        const uint32_t TA = smb + (uint32_t)(ch & 1) * GSTAGE;
        const uint32_t TB = TA + GTILE;
#pragma unroll
        for (int ks = 0; ks < 8; ks++) {
            uint32_t a[2][4], b[4][4];
#pragma unroll
            for (int mt = 0; mt < 2; mt++)
                ldsm4t(a[mt], TA + (uint32_t)((ks * 16 + (grp >> 1) * 8 + lr) * GPAD
                                              + (wm * 32 + mt * 16 + (grp & 1) * 8) * 2));
#pragma unroll
            for (int p = 0; p < 4; p++)
                ldsm4t(b[p], TB + (uint32_t)((ks * 16 + (grp & 1) * 8 + lr) * GPAD
                                             + (wn * 64 + p * 16 + (grp >> 1) * 8) * 2));
#pragma unroll
            for (int p = 0; p < 4; p++) {
#pragma unroll
                for (int mt = 0; mt < 2; mt++) {
                    mma16(c[mt][2 * p],     a[mt], b[p][0], b[p][1]);
                    mma16(c[mt][2 * p + 1], a[mt], b[p][2], b[p][3]);
                }
            }
        }
        __syncthreads();
    }

#pragma unroll
    for (int mt = 0; mt < 2; mt++) {
        int row = c1blk * 128 + wm * 32 + mt * 16 + (lane >> 2);
#pragma unroll
        for (int nt = 0; nt < 8; nt++) {
            int col = c2blk * 128 + wn * 64 + nt * 8 + 2 * (lane & 3);
            atomicAdd(&g_G[row * CIN + col],           c[mt][nt][0]);
            atomicAdd(&g_G[row * CIN + col + 1],       c[mt][nt][1]);
            atomicAdd(&g_G[(row + 8) * CIN + col],     c[mt][nt][2]);
            atomicAdd(&g_G[(row + 8) * CIN + col + 1], c[mt][nt][3]);
        }
    }
}

// per-channel d: sumsq = sum_k w^T G w ; mean = sum_k colsum . w ; -> sa, sb
__global__ __launch_bounds__(256) void k_stats2(const float* __restrict__ gamma,
                                                const float* __restrict__ beta) {
    __shared__ float sw[KOFF][CIN];
    __shared__ float red[256];
    const int d = blockIdx.x, tid = threadIdx.x;
#pragma unroll
    for (int k = 0; k < KOFF; k++)
        sw[k][tid] = __half2float(g_Wh[(size_t)(k * COUT + d) * CIN + tid]);
    __syncthreads();

    float acc[KOFF];
#pragma unroll
    for (int k = 0; k < KOFF; k++) acc[k] = 0.f;
    for (int c1 = 0; c1 < CIN; c1++) {
        float g = g_G[c1 * CIN + tid];
#pragma unroll
        for (int k = 0; k < KOFF; k++) acc[k] += g * sw[k][c1];
    }
    float sq = 0.f, mn = 0.f;
    float cs = g_colsum[tid];
#pragma unroll
    for (int k = 0; k < KOFF; k++) {
        sq += acc[k] * sw[k][tid];
        mn += cs * sw[k][tid];
    }
    red[tid] = sq; __syncthreads();
    for (int s = 128; s > 0; s >>= 1) { if (tid < s) red[tid] += red[tid + s]; __syncthreads(); }
    float SQ = red[0]; __syncthreads();
    red[tid] = mn; __syncthreads();
    for (int s = 128; s > 0; s >>= 1) { if (tid < s) red[tid] += red[tid + s]; __syncthreads(); }
    if (tid == 0) {
        float MN = red[0] / CNTF;
        float var = SQ / CNTF - MN * MN;
        float A = gamma[d] * rsqrtf(var + 1e-5f);
        g_sa[d] = A;
        g_sb[d] = beta[d] - MN * A;
    }
}

// main GEMM (R13 core) + fused BN/ReLU epilogue
__global__ __launch_bounds__(256, 2)
void k_gemm(float* __restrict__ out) {
    extern __shared__ char smem[];
    float* s_sa = (float*)(smem + OFF_STATS);
    float* s_sb = s_sa + COUT;

    const int tid = threadIdx.x, lane = tid & 31, wid = tid >> 5;
    const int wm = wid >> 1, wn = wid & 1;
    const int bx = blockIdx.x;
    const int m0 = blockIdx.y * BM;

    if (tid < COUT) { s_sa[tid] = g_sa[tid]; s_sb[tid] = g_sb[tid]; }

    const __half* Ag = g_Xh + (size_t)m0 * CIN;
    const __half* Bg = g_Wh + (size_t)(bx * COUT) * CIN;
    const uint32_t smb = smem_u32(smem);

    int rS[2], gq[2];
#pragma unroll
    for (int i = 0; i < 2; i++) {
        int f = tid + 256 * i;
        rS[i] = f >> 2; gq[i] = f & 3;
    }

#define ISSUE(t, b) do {                                                          \
        uint32_t base = smb + (uint32_t)(b) * STAGEB;                             \
        _Pragma("unroll")                                                         \
        for (int i = 0; i < 2; i++) {                                             \
            uint32_t so = (uint32_t)(rS[i] * 80 + gq[i] * 16);                    \
            int go = rS[i] * CIN + 32 * (t) + gq[i] * 8;                          \
            cpa16(base + so,        Ag + go);                                     \
            cpa16(base + OFFB + so, Bg + go);                                     \
        }                                                                         \
        CP_COMMIT();                                                              \
    } while (0)

    float c[2][8][4];
#pragma unroll
    for (int mt = 0; mt < 2; mt++)
#pragma unroll
        for (int nt = 0; nt < 8; nt++)
#pragma unroll
            for (int l = 0; l < 4; l++) c[mt][nt][l] = 0.f;

    const int grp = lane >> 3, lr = lane & 7;
    const uint32_t aoff = (uint32_t)((wm * 32 + (grp & 1) * 8 + lr) * 80 + (grp >> 1) * 16);
    const uint32_t boff = (uint32_t)(OFFB + (wn * 64 + (grp >> 1) * 8 + lr) * 80 + (grp & 1) * 16);

    ISSUE(0, 0);
    ISSUE(1, 1);

#pragma unroll
    for (int t = 0; t < 8; t++) {
        if (t < 7) CP_WAIT1(); else CP_WAIT0();
        __syncthreads();
        if (t < 6) ISSUE(t + 2, (t + 2) % NSTAGE);

        const uint32_t stg = smb + (uint32_t)(t % NSTAGE) * STAGEB;
#pragma unroll
        for (int ks = 0; ks < 2; ks++) {
            uint32_t a[2][4], b[4][4];
            ldsm4(a[0], stg + aoff + ks * 32);
            ldsm4(a[1], stg + aoff + 16 * 80 + ks * 32);
#pragma unroll
            for (int p = 0; p < 4; p++)
                ldsm4(b[p], stg + boff + p * (16 * 80) + ks * 32);
#pragma unroll
            for (int p = 0; p < 4; p++) {
                mma16(c[0][2 * p],     a[0], b[p][0], b[p][1]);
                mma16(c[1][2 * p],     a[1], b[p][0], b[p][1]);
                mma16(c[0][2 * p + 1], a[0], b[p][2], b[p][3]);
                mma16(c[1][2 * p + 1], a[1], b[p][2], b[p][3]);
            }
        }
        __syncthreads();
    }

    // fused BN + ReLU epilogue
    float* ow = out + ((size_t)bx * NR + m0) * COUT;
#pragma unroll
    for (int mt = 0; mt < 2; mt++) {
        int r = wm * 32 + mt * 16 + (lane >> 2);
#pragma unroll
        for (int nt = 0; nt < 8; nt++) {
            int dc = wn * 64 + nt * 8 + 2 * (lane & 3);
            float a0 = s_sa[dc], a1 = s_sa[dc + 1];
            float b0 = s_sb[dc], b1 = s_sb[dc + 1];
            *(float2*)&ow[(size_t)r * COUT + dc] = make_float2(
                fmaxf(fmaf(c[mt][nt][0], a0, b0), 0.f),
                fmaxf(fmaf(c[mt][nt][1], a1, b1), 0.f));
            *(float2*)&ow[(size_t)(r + 8) * COUT + dc] = make_float2(
                fmaxf(fmaf(c[mt][nt][2], a0, b0), 0.f),
                fmaxf(fmaf(c[mt][nt][3], a1, b1), 0.f));
        }
    }
}

extern "C" void kernel_launch(void* const* d_in, const int* in_sizes, int n_in,
                              void* d_out, int out_size) {
    const float* X     = (const float*)d_in[0];
    const float* W     = (const float*)d_in[1];
    const float* gamma = (const float*)d_in[2];
    const float* beta  = (const float*)d_in[3];
    float* out = (float*)d_out;

    cudaFuncSetAttribute(k_gemm, cudaFuncAttributeMaxDynamicSharedMemorySize, SMEM_BYTES);
    cudaFuncSetAttribute(k_gram, cudaFuncAttributeMaxDynamicSharedMemorySize, GSMEM);

    k_xh<<<NR * CIN / (256 * 8), 256>>>(X);                  // launch 1 (+zero G)
    k_wt<<<1024, 256>>>(W);                                  // launch 2
    k_colsum<<<NR / 256, 256>>>();                           // launch 3
    k_gram<<<dim3(4, 64), 256, GSMEM>>>();                   // launch 4 -> profiled
    k_stats2<<<COUT, 256>>>(gamma, beta);                    // launch 5
    k_gemm<<<dim3(KOFF, NR / BM), 256, SMEM_BYTES>>>(out);   // launch 6
}